// round 15
// baseline (speedup 1.0000x reference)
#include <cuda_runtime.h>
#include <cuda_fp16.h>
#include <math.h>
#include <stdint.h>

#define BB 4
#define LL 2048
#define DM 1024
#define DI 2048
#define DTR 64
#define M_TOK (BB*LL)           // 8192

// ---------------- scratch (device globals; allocation is forbidden) ----------
__device__ __align__(256) __half g_xn   [M_TOK * DM];
__device__ __align__(256) __half g_xcraw[M_TOK * DI];
__device__ __align__(256) __half g_spz  [M_TOK * DI];
__device__ __align__(256) __half g_u    [M_TOK * DI];
__device__ __align__(256) __half g_dbl  [M_TOK * DTR];
__device__ __align__(256) unsigned short g_decay16[M_TOK * DI];
__device__ __align__(256) __half g_y    [M_TOK * DI];
__device__ __align__(256) __half g_t_in [4096*1024];
__device__ __align__(256) __half g_t_x  [64*2048];
__device__ __align__(256) __half g_t_dt [2048*64];
__device__ __align__(256) __half g_t_out[1024*2048];
__device__ __align__(256) float  g_scale[4];
__device__ __align__(256) float  g_part [4*256];

// ---------------- exact reference math ---------------------------------------
__device__ __forceinline__ float squareplus_f(float x){
    float y = fminf(fmaxf(x*x + 4.0f, 1e-6f), 1e6f);
    float r = (y > 16.0f) ? 0.125f : 0.5f;
    if (y > 64.0f)  r = 0.0625f;
    if (y > 256.0f) r = 0.03125f;
    if (y < 4.0f)   r = 1.0f;
    if (y < 1.0f)   r = 2.0f;
    if (y < 0.25f)  r = 4.0f;
#pragma unroll
    for (int i = 0; i < 3; i++){
        r = r * (1.5f - 0.5f * y * r * r);
        r = fminf(fmaxf(r, 1e-6f), 1e3f);
    }
    float s = fminf(fmaxf(y * r, 0.0f), 1e3f);
    return 0.5f * (x + s);
}

__device__ __forceinline__ unsigned short decay_u16(float z){
    float sg = 0.5f + 0.5f * z / (1.0f + fabsf(z));
    return (unsigned short)(int)rintf(sg * 32768.0f);
}

// ---------------- weight scale + quant ----------------------------------------
__global__ void k_abs4(const float* __restrict__ W0, const float* __restrict__ W1,
                       const float* __restrict__ W2, const float* __restrict__ W3,
                       int n0, int n1, int n2, int n3, float* __restrict__ partial){
    const float* W; int n;
    if      (blockIdx.y == 0){ W = W0; n = n0; }
    else if (blockIdx.y == 1){ W = W1; n = n1; }
    else if (blockIdx.y == 2){ W = W2; n = n2; }
    else                     { W = W3; n = n3; }
    __shared__ float sm[256];
    float s = 0.0f;
    for (int i = blockIdx.x * 256 + threadIdx.x; i < n; i += gridDim.x * 256){
        float4 v = ((const float4*)W)[i];
        s += fabsf(v.x) + fabsf(v.y) + fabsf(v.z) + fabsf(v.w);
    }
    sm[threadIdx.x] = s; __syncthreads();
    for (int o = 128; o > 0; o >>= 1){
        if (threadIdx.x < o) sm[threadIdx.x] += sm[threadIdx.x + o];
        __syncthreads();
    }
    if (threadIdx.x == 0) partial[blockIdx.y * 256 + blockIdx.x] = sm[0];
}

__global__ void k_absfin4(const float* __restrict__ partial, float i0, float i1,
                          float i2, float i3, float* __restrict__ out){
    __shared__ float sm[256];
    int b = blockIdx.x;
    float invn = (b == 0) ? i0 : (b == 1) ? i1 : (b == 2) ? i2 : i3;
    sm[threadIdx.x] = partial[b * 256 + threadIdx.x]; __syncthreads();
    for (int o = 128; o > 0; o >>= 1){
        if (threadIdx.x < o) sm[threadIdx.x] += sm[threadIdx.x + o];
        __syncthreads();
    }
    if (threadIdx.x == 0) out[b] = sm[0] * invn + 1e-8f;
}

__global__ void k_quant(const float* __restrict__ W, __half* __restrict__ T,
                        int n4, const float* __restrict__ sp){
    float s = *sp;
    for (int i = blockIdx.x * 256 + threadIdx.x; i < n4; i += gridDim.x * 256){
        float4 v = ((const float4*)W)[i];
        float t0 = fminf(fmaxf(rintf(v.x / s), -1.0f), 1.0f);
        float t1 = fminf(fmaxf(rintf(v.y / s), -1.0f), 1.0f);
        float t2 = fminf(fmaxf(rintf(v.z / s), -1.0f), 1.0f);
        float t3 = fminf(fmaxf(rintf(v.w / s), -1.0f), 1.0f);
        __half2 p0 = __floats2half2_rn(t0, t1);
        __half2 p1 = __floats2half2_rn(t2, t3);
        uint2 u; u.x = *(uint32_t*)&p0; u.y = *(uint32_t*)&p1;
        ((uint2*)T)[i] = u;
    }
}

// ---------------- bitshift norm: warp-per-row, shuffle-only -------------------
__global__ void k_norm(const float* __restrict__ x, const float* __restrict__ gamma,
                       const float* __restrict__ step, __half* __restrict__ xn){
    int lane = threadIdx.x & 31, w = threadIdx.x >> 5;
    int row = blockIdx.x * 8 + w;
    const float4* xr = (const float4*)(x + (size_t)row * DM);
    float4 v[8];
    float s1 = 0.f, s2 = 0.f;
#pragma unroll
    for (int i = 0; i < 8; i++){
        v[i] = xr[lane + 32*i];
        s1 += v[i].x + v[i].y + v[i].z + v[i].w;
        s2 += v[i].x*v[i].x + v[i].y*v[i].y + v[i].z*v[i].z + v[i].w*v[i].w;
    }
#pragma unroll
    for (int o = 16; o > 0; o >>= 1){
        s1 += __shfl_xor_sync(0xffffffffu, s1, o);
        s2 += __shfl_xor_sync(0xffffffffu, s2, o);
    }
    float mean = s1 * (1.0f / DM);
    float var = s2 * (1.0f / DM) - mean * mean;
    float vv = var + 1e-9f;
    float sc = 1.0f;
    if (vv >= 4.0f)     sc = 0.5f;
    if (vv >= 16.0f)    sc = 0.25f;
    if (vv >= 64.0f)    sc = 0.125f;
    if (vv >= 256.0f)   sc = 0.0625f;
    if (vv >= 1024.0f)  sc = 0.03125f;
    if (vv >= 4096.0f)  sc = 0.015625f;
    if (vv >= 16384.0f) sc = 0.0078125f;
    if (vv >= 65536.0f) sc = 0.00390625f;
    if (vv < 1.0f)      sc = 1.0f;
    if (vv < 0.25f)     sc = 2.0f;
    if (vv < 0.0625f)   sc = 4.0f;
    float g = sc * step[0];
    const float4* gm4 = (const float4*)gamma;
    uint2* dst = (uint2*)(xn + (size_t)row * DM);
#pragma unroll
    for (int i = 0; i < 8; i++){
        float4 gm = gm4[lane + 32*i];
        __half2 p0 = __floats2half2_rn((v[i].x-mean)*g*gm.x, (v[i].y-mean)*g*gm.y);
        __half2 p1 = __floats2half2_rn((v[i].z-mean)*g*gm.z, (v[i].w-mean)*g*gm.w);
        uint2 uu; uu.x = *(uint32_t*)&p0; uu.y = *(uint32_t*)&p1;
        dst[lane + 32*i] = uu;
    }
}

// =================== MMA building blocks ======================================
#define RSG 40                    /* padded smem row stride (half elems) */
#define RSE 136                   /* epilogue stage row stride (half elems), 272B = 17 uint4 */

__device__ __forceinline__ void cp16(uint32_t saddr, const void* gptr){
    asm volatile("cp.async.cg.shared.global [%0],[%1],16;\n" :: "r"(saddr), "l"(gptr));
}
__device__ __forceinline__ void ldsm4(uint32_t* r, uint32_t a){
    asm volatile("ldmatrix.sync.aligned.m8n8.x4.shared.b16 {%0,%1,%2,%3},[%4];\n"
        : "=r"(r[0]), "=r"(r[1]), "=r"(r[2]), "=r"(r[3]) : "r"(a));
}
__device__ __forceinline__ void mma16816(float* c, const uint32_t* a, uint32_t b0, uint32_t b1){
    asm volatile(
        "mma.sync.aligned.m16n8k16.row.col.f32.f16.f16.f32 "
        "{%0,%1,%2,%3},{%4,%5,%6,%7},{%8,%9},{%0,%1,%2,%3};\n"
        : "+f"(c[0]), "+f"(c[1]), "+f"(c[2]), "+f"(c[3])
        : "r"(a[0]), "r"(a[1]), "r"(a[2]), "r"(a[3]), "r"(b0), "r"(b1));
}

// =================== fp16 GEMM, 256 threads, BK=32, 4-stage pipeline ==========
template<int BM, int BN>
__device__ __forceinline__ void ld_stage(uint32_t sbase, const __half* __restrict__ A,
                                         const __half* __restrict__ Bw,
                                         int m0, int n0, int K, int kb, int tid){
    constexpr int A_SZ = BM * RSG;
#pragma unroll
    for (int j = 0; j < BM*4/256; j++){
        int idx = tid + j*256;
        int r = idx >> 2, sg = (idx & 3) * 8;
        cp16(sbase + (uint32_t)(r*RSG + sg)*2, A + (size_t)(m0 + r)*K + kb + sg);
    }
#pragma unroll
    for (int j = 0; j < BN*4/256; j++){
        int idx = tid + j*256;
        int r = idx >> 2, sg = (idx & 3) * 8;
        cp16(sbase + (uint32_t)(A_SZ + r*RSG + sg)*2, Bw + (size_t)(n0 + r)*K + kb + sg);
    }
    asm volatile("cp.async.commit_group;\n" ::);
}

// EPI: 1 decay->u16 (smem-staged) | 2 +resid->C0f | 3 fp16 -> H0 |
//      4 split xcraw|spz fp16 (smem-staged)
template<int BM, int BN, int EPI>
__global__ __launch_bounds__(256, 2)
void k_gemm_h(const __half* __restrict__ A, const __half* __restrict__ Bw,
              int M, int N, int K,
              const float* __restrict__ scale_p,
              const float* __restrict__ bias,
              const float* __restrict__ resid,
              float* __restrict__ C0f,
              __half* __restrict__ H0, __half* __restrict__ H1,
              unsigned short* __restrict__ U16){
    constexpr int A_SZ = BM * RSG;
    constexpr int B_SZ = BN * RSG;
    constexpr int STG  = A_SZ + B_SZ;
    constexpr int NG = BN / 32;
    constexpr int NT = BN / 16;
    constexpr int MT = BM / 64;
    extern __shared__ __align__(16) __half smem[];

    const int tid = threadIdx.x;
    const int m0 = blockIdx.y * BM, n0 = blockIdx.x * BN;
    const int lane = tid & 31, w = tid >> 5;
    const int wm = w >> 1, wn = w & 1;
    const int m0w = wm * (16*MT), n0w = wn * (BN/2);

    float acc[MT][NT][4];
#pragma unroll
    for (int i = 0; i < MT; i++)
#pragma unroll
        for (int j = 0; j < NT; j++)
#pragma unroll
            for (int q = 0; q < 4; q++) acc[i][j][q] = 0.0f;

    const int aoff = (m0w + (lane & 15)) * RSG + (lane >> 4) * 8;
    const int boff = (n0w + ((lane >> 4) << 3) + (lane & 7)) * RSG + ((lane >> 3) & 1) * 8;
    const int NITER = K / 32;
    uint32_t sb = (uint32_t)__cvta_generic_to_shared(smem);

    ld_stage<BM,BN>(sb, A, Bw, m0, n0, K, 0, tid);
    if (NITER > 1) ld_stage<BM,BN>(sb + (uint32_t)STG*2, A, Bw, m0, n0, K, 32, tid);
    if (NITER > 2) ld_stage<BM,BN>(sb + (uint32_t)STG*4, A, Bw, m0, n0, K, 64, tid);

    for (int it = 0; it < NITER; it++){
        if      (it + 3 <= NITER) asm volatile("cp.async.wait_group 2;\n" ::);
        else if (it + 2 <= NITER) asm volatile("cp.async.wait_group 1;\n" ::);
        else                      asm volatile("cp.async.wait_group 0;\n" ::);
        __syncthreads();
        if (it + 3 < NITER)
            ld_stage<BM,BN>(sb + (uint32_t)(((it+3)&3)*STG)*2, A, Bw, m0, n0, K, (it+3)*32, tid);

        uint32_t sbase = sb + (uint32_t)((it&3)*STG)*2;
#pragma unroll
        for (int ks = 0; ks < 2; ks++){
            int ko = ks * 16;
            uint32_t ah[MT][4], bq[NG][4];
#pragma unroll
            for (int mt = 0; mt < MT; mt++)
                ldsm4(ah[mt], sbase + (uint32_t)(aoff + mt*16*RSG + ko)*2);
#pragma unroll
            for (int j = 0; j < NG; j++)
                ldsm4(bq[j], sbase + (uint32_t)(A_SZ + boff + j*16*RSG + ko)*2);
#pragma unroll
            for (int j = 0; j < NG; j++)
#pragma unroll
                for (int mt = 0; mt < MT; mt++){
                    mma16816(acc[mt][2*j],   ah[mt], bq[j][0], bq[j][1]);
                    mma16816(acc[mt][2*j+1], ah[mt], bq[j][2], bq[j][3]);
                }
        }
    }

    float s = *scale_p;
    if (EPI == 4 || EPI == 1){
        // ---- smem-staged epilogue: full-sector coalesced stores --------------
        __syncthreads();                 // stage buffers are dead; reuse smem
        bool zhalf = (EPI == 4) && (n0 >= DI);
#pragma unroll
        for (int mt = 0; mt < MT; mt++){
            int r0l = m0w + mt*16 + (lane >> 2);
            int r1l = r0l + 8;
#pragma unroll
            for (int nt = 0; nt < NT; nt++){
                int cl = n0w + nt*8 + (lane & 3)*2;
                float v0 = acc[mt][nt][0]*s, v1 = acc[mt][nt][1]*s;
                float v2 = acc[mt][nt][2]*s, v3 = acc[mt][nt][3]*s;
                uint32_t d0, d1;
                if (EPI == 1){
                    d0 = (uint32_t)decay_u16(v0 + bias[n0 + cl])
                       | ((uint32_t)decay_u16(v1 + bias[n0 + cl + 1]) << 16);
                    d1 = (uint32_t)decay_u16(v2 + bias[n0 + cl])
                       | ((uint32_t)decay_u16(v3 + bias[n0 + cl + 1]) << 16);
                } else if (zhalf){
                    __half2 p0 = __floats2half2_rn(squareplus_f(v0), squareplus_f(v1));
                    __half2 p1 = __floats2half2_rn(squareplus_f(v2), squareplus_f(v3));
                    d0 = *(uint32_t*)&p0; d1 = *(uint32_t*)&p1;
                } else {
                    __half2 p0 = __floats2half2_rn(v0, v1);
                    __half2 p1 = __floats2half2_rn(v2, v3);
                    d0 = *(uint32_t*)&p0; d1 = *(uint32_t*)&p1;
                }
                *(uint32_t*)&smem[r0l*RSE + cl] = d0;
                *(uint32_t*)&smem[r1l*RSE + cl] = d1;
            }
        }
        __syncthreads();
        // copy out: half-warp per row, 16 x uint4 = 256B contiguous per row
        const uint4* s4 = (const uint4*)smem;
#pragma unroll
        for (int iter = 0; iter < BM/16; iter++){
            int row = iter*16 + w*2 + (lane >> 4);
            int cu  = lane & 15;
            uint4 v = s4[row*(RSE/8)* /*17 uint4*/ 1 + cu];  // RSE halfs = 17 uint4
            // note: RSE = 136 halfs = 272B = 17 uint4 rows
            v = s4[row*17 + cu];
            if (EPI == 1){
                size_t off = (size_t)(m0 + row)*N + n0;
                ((uint4*)(U16 + off))[cu] = v;
            } else {
                __half* dstb = zhalf ? H1 : H0;
                size_t off = (size_t)(m0 + row)*DI + (zhalf ? (n0 - DI) : n0);
                ((uint4*)(dstb + off))[cu] = v;
            }
        }
    } else {
#pragma unroll
        for (int mt = 0; mt < MT; mt++){
            int r0 = m0 + m0w + mt*16 + (lane >> 2);
            int r1 = r0 + 8;
#pragma unroll
            for (int nt = 0; nt < NT; nt++){
                int c = n0 + n0w + nt*8 + (lane & 3)*2;
                float v0 = acc[mt][nt][0]*s, v1 = acc[mt][nt][1]*s;
                float v2 = acc[mt][nt][2]*s, v3 = acc[mt][nt][3]*s;
                if (EPI == 2){
                    float2 f0 = make_float2(v0 + resid[(size_t)r0*N + c],
                                            v1 + resid[(size_t)r0*N + c+1]);
                    float2 f1 = make_float2(v2 + resid[(size_t)r1*N + c],
                                            v3 + resid[(size_t)r1*N + c+1]);
                    *(float2*)&C0f[(size_t)r0*N + c] = f0;
                    *(float2*)&C0f[(size_t)r1*N + c] = f1;
                } else { // EPI == 3
                    __half2 p0 = __floats2half2_rn(v0, v1);
                    __half2 p1 = __floats2half2_rn(v2, v3);
                    *(uint32_t*)&H0[(size_t)r0*N + c] = *(uint32_t*)&p0;
                    *(uint32_t*)&H0[(size_t)r1*N + c] = *(uint32_t*)&p1;
                }
            }
        }
    }
}

// ---------------- causal depthwise conv1d(k=4) + squareplus (8ch/thread) -----
__global__ void k_conv(const __half* __restrict__ xcraw, const float* __restrict__ cw,
                       const float* __restrict__ cb, __half* __restrict__ u){
    int i = blockIdx.x * 256 + threadIdx.x;
    int idx = i * 8;
    int d0 = idx & (DI - 1);
    int m = idx >> 11;
    int t = m & (LL - 1);
    const uint4* x8 = (const uint4*)xcraw;
    uint4 z4 = make_uint4(0u,0u,0u,0u);
    uint4 q0 = x8[i];
    uint4 q1 = (t >= 1) ? x8[i - DI/8]   : z4;
    uint4 q2 = (t >= 2) ? x8[i - 2*DI/8] : z4;
    uint4 q3 = (t >= 3) ? x8[i - 3*DI/8] : z4;
    const __half2* h0 = (const __half2*)&q0;
    const __half2* h1 = (const __half2*)&q1;
    const __half2* h2 = (const __half2*)&q2;
    const __half2* h3 = (const __half2*)&q3;
    uint4 outv;
    __half2* ov = (__half2*)&outv;
#pragma unroll
    for (int p = 0; p < 4; p++){
        int da = d0 + p*2, db = da + 1;
        float4 wA = ((const float4*)cw)[da];
        float4 wB = ((const float4*)cw)[db];
        float2 cb2 = ((const float2*)cb)[(d0 >> 1) + p];
        float xa0 = __low2float(h0[p]),  xb0 = __high2float(h0[p]);
        float xa1 = __low2float(h1[p]),  xb1 = __high2float(h1[p]);
        float xa2 = __low2float(h2[p]),  xb2 = __high2float(h2[p]);
        float xa3 = __low2float(h3[p]),  xb3 = __high2float(h3[p]);
        float sa = cb2.x + wA.w*xa0 + wA.z*xa1 + wA.y*xa2 + wA.x*xa3;
        float sbv = cb2.y + wB.w*xb0 + wB.z*xb1 + wB.y*xb2 + wB.x*xb3;
        ov[p] = __floats2half2_rn(squareplus_f(sa), squareplus_f(sbv));
    }
    ((uint4*)u)[i] = outv;
}

// ---------------- chunked scan (coalesced, 2 ch/thread) ----------------------
__global__ void k_scan(const __half* __restrict__ u,
                       const unsigned short* __restrict__ a16,
                       const __half* __restrict__ spz,
                       __half* __restrict__ y){
    const int tx = threadIdx.x;
    const int c0 = (blockIdx.x * 32 + tx) * 2;
    const int b = blockIdx.y;
    const int slice = threadIdx.y;
    const int CH = LL / 32;                        // 64
    size_t base = ((size_t)b * LL) * DI + c0;
    int t0 = slice * CH;

    float A0 = 1.0f, B0 = 0.0f, A1 = 1.0f, B1 = 0.0f;
    size_t idx = base + (size_t)t0 * DI;
    for (int t = 0; t < CH; t++, idx += DI){
        uint32_t aa = *(const uint32_t*)(a16 + idx);
        float at0 = (float)(aa & 0xFFFFu) * (1.0f/32768.0f);
        float at1 = (float)(aa >> 16)     * (1.0f/32768.0f);
        __half2 uh = *(const __half2*)(u + idx);
        float u0 = __low2float(uh), u1 = __high2float(uh);
        B0 = at0 * B0 + (1.0f - at0) * u0; A0 *= at0;
        B1 = at1 * B1 + (1.0f - at1) * u1; A1 *= at1;
    }
    __shared__ float2 sA[32][32], sB[32][32], sP[32][32];
    sA[slice][tx] = make_float2(A0, A1);
    sB[slice][tx] = make_float2(B0, B1);
    __syncthreads();
    if (slice == 0){
        float2 carry = make_float2(0.0f, 0.0f);
#pragma unroll
        for (int s2 = 0; s2 < 32; s2++){
            sP[s2][tx] = carry;
            float2 a = sA[s2][tx], bb = sB[s2][tx];
            carry.x = a.x * carry.x + bb.x;
            carry.y = a.y * carry.y + bb.y;
        }
    }
    __syncthreads();
    float2 h = sP[slice][tx];
    idx = base + (size_t)t0 * DI;
    for (int t = 0; t < CH; t++, idx += DI){
        uint32_t aa = *(const uint32_t*)(a16 + idx);
        float at0 = (float)(aa & 0xFFFFu) * (1.0f/32768.0f);
        float at1 = (float)(aa >> 16)     * (1.0f/32768.0f);
        __half2 uh = *(const __half2*)(u + idx);
        h.x = at0 * h.x + (1.0f - at0) * __low2float(uh);
        h.y = at1 * h.y + (1.0f - at1) * __high2float(uh);
        __half2 sz = *(const __half2*)(spz + idx);
        __half2 yy = __floats2half2_rn(h.x * __low2float(sz), h.y * __high2float(sz));
        *(__half2*)(y + idx) = yy;
    }
}

// ---------------- launch ------------------------------------------------------
extern "C" void kernel_launch(void* const* d_in, const int* in_sizes, int n_in,
                              void* d_out, int out_size){
    const float* x     = (const float*)d_in[0];
    const float* gamma = (const float*)d_in[1];
    const float* step  = (const float*)d_in[2];
    const float* W_in  = (const float*)d_in[3];
    const float* cw    = (const float*)d_in[4];
    const float* cb    = (const float*)d_in[5];
    const float* W_x   = (const float*)d_in[6];
    const float* W_dt  = (const float*)d_in[7];
    const float* b_dt  = (const float*)d_in[8];
    const float* W_out = (const float*)d_in[9];
    float* out = (float*)d_out;

    __half *p_xn, *p_xcraw, *p_spz, *p_u, *p_dbl, *p_y;
    __half *p_tin, *p_tx, *p_tdt, *p_tout;
    float *p_scale, *p_part;
    unsigned short* p_decay;
    cudaGetSymbolAddress((void**)&p_xn,    g_xn);
    cudaGetSymbolAddress((void**)&p_xcraw, g_xcraw);
    cudaGetSymbolAddress((void**)&p_spz,   g_spz);
    cudaGetSymbolAddress((void**)&p_u,     g_u);
    cudaGetSymbolAddress((void**)&p_dbl,   g_dbl);
    cudaGetSymbolAddress((void**)&p_decay, g_decay16);
    cudaGetSymbolAddress((void**)&p_y,     g_y);
    cudaGetSymbolAddress((void**)&p_tin,   g_t_in);
    cudaGetSymbolAddress((void**)&p_tx,    g_t_x);
    cudaGetSymbolAddress((void**)&p_tdt,   g_t_dt);
    cudaGetSymbolAddress((void**)&p_tout,  g_t_out);
    cudaGetSymbolAddress((void**)&p_scale, g_scale);
    cudaGetSymbolAddress((void**)&p_part,  g_part);

    // 4-stage mainloop smem; EPI1/4 stage needs 128*136*2 = 34816 <= SM128
    const int SM128 = 4*(128*RSG + 128*RSG)*2;   // 81920
    const int SM64  = 4*( 64*RSG +  64*RSG)*2;   // 40960
    cudaFuncSetAttribute(k_gemm_h<128,128,4>, cudaFuncAttributeMaxDynamicSharedMemorySize, SM128);
    cudaFuncSetAttribute(k_gemm_h< 64, 64,3>, cudaFuncAttributeMaxDynamicSharedMemorySize, SM64);
    cudaFuncSetAttribute(k_gemm_h<128,128,1>, cudaFuncAttributeMaxDynamicSharedMemorySize, SM128);
    cudaFuncSetAttribute(k_gemm_h<128,128,2>, cudaFuncAttributeMaxDynamicSharedMemorySize, SM128);

    // --- second stream for the weight-quant chain ------------------------------
    cudaStream_t s1;
    cudaStreamCreateWithFlags(&s1, cudaStreamNonBlocking);
    cudaEvent_t e0, e_in, e_w;
    cudaEventCreateWithFlags(&e0,   cudaEventDisableTiming);
    cudaEventCreateWithFlags(&e_in, cudaEventDisableTiming);
    cudaEventCreateWithFlags(&e_w,  cudaEventDisableTiming);

    cudaEventRecord(e0, 0);
    cudaStreamWaitEvent(s1, e0, 0);

    // s1: scales, then W_in quant (gates GEMM1), then the rest (hidden by GEMM1)
    k_abs4<<<dim3(256,4),256,0,s1>>>(W_in, W_x, W_dt, W_out,
                                     4096*1024/4, 96*2048/4, 2048*64/4, 1024*2048/4, p_part);
    k_absfin4<<<4,256,0,s1>>>(p_part, 1.0f/4194304.0f, 1.0f/196608.0f,
                              1.0f/131072.0f, 1.0f/2097152.0f, p_scale);
    k_quant<<<1024,256,0,s1>>>(W_in, p_tin, 4194304/4, p_scale + 0);
    cudaEventRecord(e_in, s1);
    k_quant<<<128,256,0,s1>>>(W_x,  p_tx,  131072/4,  p_scale + 1);
    k_quant<<<128,256,0,s1>>>(W_dt, p_tdt, 131072/4,  p_scale + 2);
    k_quant<<<512,256,0,s1>>>(W_out,p_tout,2097152/4, p_scale + 3);
    cudaEventRecord(e_w, s1);

    // s0 (default): norm overlaps the quant chain
    k_norm<<<M_TOK/8,256>>>(x, gamma, step, p_xn);

    cudaStreamWaitEvent(0, e_in, 0);
    // 3) in-projection: split xc_raw (fp16) | squareplus(z) (fp16)
    k_gemm_h<128,128,4><<<dim3(32,64),256,SM128>>>(p_xn, p_tin, M_TOK, 4096, 1024,
                                                   p_scale+0, nullptr, nullptr,
                                                   nullptr, p_xcraw, p_spz, nullptr);

    // 4) causal conv + squareplus -> u fp16
    k_conv<<<M_TOK*DI/8/256,256>>>(p_xcraw, cw, cb, p_u);

    cudaStreamWaitEvent(0, e_w, 0);
    // 5) dt_rank projection -> dbl fp16 (BM=64 -> 128 CTAs)
    k_gemm_h<64,64,3><<<dim3(1,128),256,SM64>>>(p_u, p_tx, M_TOK, 64, 2048,
                                                p_scale+1, nullptr, nullptr,
                                                nullptr, p_dbl, nullptr, nullptr);

    // 6) dt projection + fused sigmoid + dyadic round -> decay u16 (staged)
    k_gemm_h<128,128,1><<<dim3(16,64),256,SM128>>>(p_dbl, p_tdt, M_TOK, 2048, 64,
                                                   p_scale+2, b_dt, nullptr,
                                                   nullptr, nullptr, nullptr, p_decay);

    // 7) scan + fused y = h * spz -> fp16
    k_scan<<<dim3(DI/64, BB), dim3(32,32)>>>(p_u, p_decay, p_spz, p_y);

    // 8) out-projection + residual -> d_out (fp32)
    k_gemm_h<128,128,2><<<dim3(8,64),256,SM128>>>(p_y, p_tout, M_TOK, 1024, 2048,
                                                  p_scale+3, nullptr, x,
                                                  out, nullptr, nullptr, nullptr);

    cudaEventDestroy(e0);
    cudaEventDestroy(e_in);
    cudaEventDestroy(e_w);
    cudaStreamDestroy(s1);
}

// round 16
// speedup vs baseline: 1.0244x; 1.0244x over previous
#include <cuda_runtime.h>
#include <cuda_fp16.h>
#include <math.h>
#include <stdint.h>

#define BB 4
#define LL 2048
#define DM 1024
#define DI 2048
#define DTR 64
#define M_TOK (BB*LL)           // 8192
#define MH (M_TOK/2)            // 4096 rows per half (2 full batches)

// ---------------- scratch (device globals; allocation is forbidden) ----------
__device__ __align__(256) __half g_xn   [M_TOK * DM];
__device__ __align__(256) __half g_xcraw[M_TOK * DI];
__device__ __align__(256) __half g_spz  [M_TOK * DI];
__device__ __align__(256) __half g_u    [M_TOK * DI];
__device__ __align__(256) __half g_dbl  [M_TOK * DTR];
__device__ __align__(256) unsigned short g_decay16[M_TOK * DI];
__device__ __align__(256) __half g_y    [M_TOK * DI];
__device__ __align__(256) __half g_t_in [4096*1024];
__device__ __align__(256) __half g_t_x  [64*2048];
__device__ __align__(256) __half g_t_dt [2048*64];
__device__ __align__(256) __half g_t_out[1024*2048];
__device__ __align__(256) float  g_scale[4];
__device__ __align__(256) float  g_part [4*256];

// ---------------- exact reference math ---------------------------------------
__device__ __forceinline__ float squareplus_f(float x){
    float y = fminf(fmaxf(x*x + 4.0f, 1e-6f), 1e6f);
    float r = (y > 16.0f) ? 0.125f : 0.5f;
    if (y > 64.0f)  r = 0.0625f;
    if (y > 256.0f) r = 0.03125f;
    if (y < 4.0f)   r = 1.0f;
    if (y < 1.0f)   r = 2.0f;
    if (y < 0.25f)  r = 4.0f;
#pragma unroll
    for (int i = 0; i < 3; i++){
        r = r * (1.5f - 0.5f * y * r * r);
        r = fminf(fmaxf(r, 1e-6f), 1e3f);
    }
    float s = fminf(fmaxf(y * r, 0.0f), 1e3f);
    return 0.5f * (x + s);
}

__device__ __forceinline__ unsigned short decay_u16(float z){
    float sg = 0.5f + 0.5f * z / (1.0f + fabsf(z));
    return (unsigned short)(int)rintf(sg * 32768.0f);
}

// ---------------- weight scale + quant ----------------------------------------
__global__ void k_abs4(const float* __restrict__ W0, const float* __restrict__ W1,
                       const float* __restrict__ W2, const float* __restrict__ W3,
                       int n0, int n1, int n2, int n3, float* __restrict__ partial){
    const float* W; int n;
    if      (blockIdx.y == 0){ W = W0; n = n0; }
    else if (blockIdx.y == 1){ W = W1; n = n1; }
    else if (blockIdx.y == 2){ W = W2; n = n2; }
    else                     { W = W3; n = n3; }
    __shared__ float sm[256];
    float s = 0.0f;
    for (int i = blockIdx.x * 256 + threadIdx.x; i < n; i += gridDim.x * 256){
        float4 v = ((const float4*)W)[i];
        s += fabsf(v.x) + fabsf(v.y) + fabsf(v.z) + fabsf(v.w);
    }
    sm[threadIdx.x] = s; __syncthreads();
    for (int o = 128; o > 0; o >>= 1){
        if (threadIdx.x < o) sm[threadIdx.x] += sm[threadIdx.x + o];
        __syncthreads();
    }
    if (threadIdx.x == 0) partial[blockIdx.y * 256 + blockIdx.x] = sm[0];
}

__global__ void k_absfin4(const float* __restrict__ partial, float i0, float i1,
                          float i2, float i3, float* __restrict__ out){
    __shared__ float sm[256];
    int b = blockIdx.x;
    float invn = (b == 0) ? i0 : (b == 1) ? i1 : (b == 2) ? i2 : i3;
    sm[threadIdx.x] = partial[b * 256 + threadIdx.x]; __syncthreads();
    for (int o = 128; o > 0; o >>= 1){
        if (threadIdx.x < o) sm[threadIdx.x] += sm[threadIdx.x + o];
        __syncthreads();
    }
    if (threadIdx.x == 0) out[b] = sm[0] * invn + 1e-8f;
}

__global__ void k_quant(const float* __restrict__ W, __half* __restrict__ T,
                        int n4, const float* __restrict__ sp){
    float s = *sp;
    for (int i = blockIdx.x * 256 + threadIdx.x; i < n4; i += gridDim.x * 256){
        float4 v = ((const float4*)W)[i];
        float t0 = fminf(fmaxf(rintf(v.x / s), -1.0f), 1.0f);
        float t1 = fminf(fmaxf(rintf(v.y / s), -1.0f), 1.0f);
        float t2 = fminf(fmaxf(rintf(v.z / s), -1.0f), 1.0f);
        float t3 = fminf(fmaxf(rintf(v.w / s), -1.0f), 1.0f);
        __half2 p0 = __floats2half2_rn(t0, t1);
        __half2 p1 = __floats2half2_rn(t2, t3);
        uint2 u; u.x = *(uint32_t*)&p0; u.y = *(uint32_t*)&p1;
        ((uint2*)T)[i] = u;
    }
}

// ---------------- bitshift norm: warp-per-row, shuffle-only -------------------
__global__ void k_norm(const float* __restrict__ x, const float* __restrict__ gamma,
                       const float* __restrict__ step, __half* __restrict__ xn){
    int lane = threadIdx.x & 31, w = threadIdx.x >> 5;
    int row = blockIdx.x * 8 + w;
    const float4* xr = (const float4*)(x + (size_t)row * DM);
    float4 v[8];
    float s1 = 0.f, s2 = 0.f;
#pragma unroll
    for (int i = 0; i < 8; i++){
        v[i] = xr[lane + 32*i];
        s1 += v[i].x + v[i].y + v[i].z + v[i].w;
        s2 += v[i].x*v[i].x + v[i].y*v[i].y + v[i].z*v[i].z + v[i].w*v[i].w;
    }
#pragma unroll
    for (int o = 16; o > 0; o >>= 1){
        s1 += __shfl_xor_sync(0xffffffffu, s1, o);
        s2 += __shfl_xor_sync(0xffffffffu, s2, o);
    }
    float mean = s1 * (1.0f / DM);
    float var = s2 * (1.0f / DM) - mean * mean;
    float vv = var + 1e-9f;
    float sc = 1.0f;
    if (vv >= 4.0f)     sc = 0.5f;
    if (vv >= 16.0f)    sc = 0.25f;
    if (vv >= 64.0f)    sc = 0.125f;
    if (vv >= 256.0f)   sc = 0.0625f;
    if (vv >= 1024.0f)  sc = 0.03125f;
    if (vv >= 4096.0f)  sc = 0.015625f;
    if (vv >= 16384.0f) sc = 0.0078125f;
    if (vv >= 65536.0f) sc = 0.00390625f;
    if (vv < 1.0f)      sc = 1.0f;
    if (vv < 0.25f)     sc = 2.0f;
    if (vv < 0.0625f)   sc = 4.0f;
    float g = sc * step[0];
    const float4* gm4 = (const float4*)gamma;
    uint2* dst = (uint2*)(xn + (size_t)row * DM);
#pragma unroll
    for (int i = 0; i < 8; i++){
        float4 gm = gm4[lane + 32*i];
        __half2 p0 = __floats2half2_rn((v[i].x-mean)*g*gm.x, (v[i].y-mean)*g*gm.y);
        __half2 p1 = __floats2half2_rn((v[i].z-mean)*g*gm.z, (v[i].w-mean)*g*gm.w);
        uint2 uu; uu.x = *(uint32_t*)&p0; uu.y = *(uint32_t*)&p1;
        dst[lane + 32*i] = uu;
    }
}

// =================== MMA building blocks ======================================
#define RSG 40                    /* padded smem row stride (half elems) */

__device__ __forceinline__ void cp16(uint32_t saddr, const void* gptr){
    asm volatile("cp.async.cg.shared.global [%0],[%1],16;\n" :: "r"(saddr), "l"(gptr));
}
__device__ __forceinline__ void ldsm4(uint32_t* r, uint32_t a){
    asm volatile("ldmatrix.sync.aligned.m8n8.x4.shared.b16 {%0,%1,%2,%3},[%4];\n"
        : "=r"(r[0]), "=r"(r[1]), "=r"(r[2]), "=r"(r[3]) : "r"(a));
}
__device__ __forceinline__ void mma16816(float* c, const uint32_t* a, uint32_t b0, uint32_t b1){
    asm volatile(
        "mma.sync.aligned.m16n8k16.row.col.f32.f16.f16.f32 "
        "{%0,%1,%2,%3},{%4,%5,%6,%7},{%8,%9},{%0,%1,%2,%3};\n"
        : "+f"(c[0]), "+f"(c[1]), "+f"(c[2]), "+f"(c[3])
        : "r"(a[0]), "r"(a[1]), "r"(a[2]), "r"(a[3]), "r"(b0), "r"(b1));
}

// =================== fp16 GEMM, 256 threads, BK=32, 4-stage pipeline ==========
template<int BM, int BN>
__device__ __forceinline__ void ld_stage(uint32_t sbase, const __half* __restrict__ A,
                                         const __half* __restrict__ Bw,
                                         int m0, int n0, int K, int kb, int tid){
    constexpr int A_SZ = BM * RSG;
#pragma unroll
    for (int j = 0; j < BM*4/256; j++){
        int idx = tid + j*256;
        int r = idx >> 2, sg = (idx & 3) * 8;
        cp16(sbase + (uint32_t)(r*RSG + sg)*2, A + (size_t)(m0 + r)*K + kb + sg);
    }
#pragma unroll
    for (int j = 0; j < BN*4/256; j++){
        int idx = tid + j*256;
        int r = idx >> 2, sg = (idx & 3) * 8;
        cp16(sbase + (uint32_t)(A_SZ + r*RSG + sg)*2, Bw + (size_t)(n0 + r)*K + kb + sg);
    }
    asm volatile("cp.async.commit_group;\n" ::);
}

// EPI: 1 decay->u16 | 2 +resid->C0f | 3 fp16 -> H0 | 4 split xcraw|spz (fp16)
template<int BM, int BN, int EPI>
__global__ __launch_bounds__(256, 2)
void k_gemm_h(const __half* __restrict__ A, const __half* __restrict__ Bw,
              int M, int N, int K,
              const float* __restrict__ scale_p,
              const float* __restrict__ bias,
              const float* __restrict__ resid,
              float* __restrict__ C0f,
              __half* __restrict__ H0, __half* __restrict__ H1,
              unsigned short* __restrict__ U16){
    constexpr int A_SZ = BM * RSG;
    constexpr int B_SZ = BN * RSG;
    constexpr int STG  = A_SZ + B_SZ;
    constexpr int NG = BN / 32;
    constexpr int NT = BN / 16;
    constexpr int MT = BM / 64;
    extern __shared__ __align__(16) __half smem[];

    const int tid = threadIdx.x;
    const int m0 = blockIdx.y * BM, n0 = blockIdx.x * BN;
    const int lane = tid & 31, w = tid >> 5;
    const int wm = w >> 1, wn = w & 1;
    const int m0w = wm * (16*MT), n0w = wn * (BN/2);

    float acc[MT][NT][4];
#pragma unroll
    for (int i = 0; i < MT; i++)
#pragma unroll
        for (int j = 0; j < NT; j++)
#pragma unroll
            for (int q = 0; q < 4; q++) acc[i][j][q] = 0.0f;

    const int aoff = (m0w + (lane & 15)) * RSG + (lane >> 4) * 8;
    const int boff = (n0w + ((lane >> 4) << 3) + (lane & 7)) * RSG + ((lane >> 3) & 1) * 8;
    const int NITER = K / 32;
    uint32_t sb = (uint32_t)__cvta_generic_to_shared(smem);

    ld_stage<BM,BN>(sb, A, Bw, m0, n0, K, 0, tid);
    if (NITER > 1) ld_stage<BM,BN>(sb + (uint32_t)STG*2, A, Bw, m0, n0, K, 32, tid);
    if (NITER > 2) ld_stage<BM,BN>(sb + (uint32_t)STG*4, A, Bw, m0, n0, K, 64, tid);

    for (int it = 0; it < NITER; it++){
        if      (it + 3 <= NITER) asm volatile("cp.async.wait_group 2;\n" ::);
        else if (it + 2 <= NITER) asm volatile("cp.async.wait_group 1;\n" ::);
        else                      asm volatile("cp.async.wait_group 0;\n" ::);
        __syncthreads();
        if (it + 3 < NITER)
            ld_stage<BM,BN>(sb + (uint32_t)(((it+3)&3)*STG)*2, A, Bw, m0, n0, K, (it+3)*32, tid);

        uint32_t sbase = sb + (uint32_t)((it&3)*STG)*2;
#pragma unroll
        for (int ks = 0; ks < 2; ks++){
            int ko = ks * 16;
            uint32_t ah[MT][4], bq[NG][4];
#pragma unroll
            for (int mt = 0; mt < MT; mt++)
                ldsm4(ah[mt], sbase + (uint32_t)(aoff + mt*16*RSG + ko)*2);
#pragma unroll
            for (int j = 0; j < NG; j++)
                ldsm4(bq[j], sbase + (uint32_t)(A_SZ + boff + j*16*RSG + ko)*2);
#pragma unroll
            for (int j = 0; j < NG; j++)
#pragma unroll
                for (int mt = 0; mt < MT; mt++){
                    mma16816(acc[mt][2*j],   ah[mt], bq[j][0], bq[j][1]);
                    mma16816(acc[mt][2*j+1], ah[mt], bq[j][2], bq[j][3]);
                }
        }
    }

    float s = *scale_p;
#pragma unroll
    for (int mt = 0; mt < MT; mt++){
        int r0 = m0 + m0w + mt*16 + (lane >> 2);
        int r1 = r0 + 8;
#pragma unroll
        for (int nt = 0; nt < NT; nt++){
            int c = n0 + n0w + nt*8 + (lane & 3)*2;
            float v0 = acc[mt][nt][0]*s, v1 = acc[mt][nt][1]*s;
            float v2 = acc[mt][nt][2]*s, v3 = acc[mt][nt][3]*s;
            if (EPI == 1){
                uint32_t d0 = (uint32_t)decay_u16(v0 + bias[c])
                            | ((uint32_t)decay_u16(v1 + bias[c+1]) << 16);
                uint32_t d1 = (uint32_t)decay_u16(v2 + bias[c])
                            | ((uint32_t)decay_u16(v3 + bias[c+1]) << 16);
                *(uint32_t*)&U16[(size_t)r0*N + c] = d0;
                *(uint32_t*)&U16[(size_t)r1*N + c] = d1;
            } else if (EPI == 2){
                float2 f0 = make_float2(v0 + resid[(size_t)r0*N + c],
                                        v1 + resid[(size_t)r0*N + c+1]);
                float2 f1 = make_float2(v2 + resid[(size_t)r1*N + c],
                                        v3 + resid[(size_t)r1*N + c+1]);
                *(float2*)&C0f[(size_t)r0*N + c] = f0;
                *(float2*)&C0f[(size_t)r1*N + c] = f1;
            } else if (EPI == 3){
                __half2 p0 = __floats2half2_rn(v0, v1);
                __half2 p1 = __floats2half2_rn(v2, v3);
                *(uint32_t*)&H0[(size_t)r0*N + c] = *(uint32_t*)&p0;
                *(uint32_t*)&H0[(size_t)r1*N + c] = *(uint32_t*)&p1;
            } else {  // EPI == 4
                if (c < DI){
                    __half2 p0 = __floats2half2_rn(v0, v1);
                    __half2 p1 = __floats2half2_rn(v2, v3);
                    *(uint32_t*)&H0[(size_t)r0*DI + c] = *(uint32_t*)&p0;
                    *(uint32_t*)&H0[(size_t)r1*DI + c] = *(uint32_t*)&p1;
                } else {
                    int cc = c - DI;
                    __half2 p0 = __floats2half2_rn(squareplus_f(v0), squareplus_f(v1));
                    __half2 p1 = __floats2half2_rn(squareplus_f(v2), squareplus_f(v3));
                    *(uint32_t*)&H1[(size_t)r0*DI + cc] = *(uint32_t*)&p0;
                    *(uint32_t*)&H1[(size_t)r1*DI + cc] = *(uint32_t*)&p1;
                }
            }
        }
    }
}

// ---------------- causal depthwise conv1d(k=4) + squareplus (8ch/thread) -----
__global__ void k_conv(const __half* __restrict__ xcraw, const float* __restrict__ cw,
                       const float* __restrict__ cb, __half* __restrict__ u){
    int i = blockIdx.x * 256 + threadIdx.x;
    int idx = i * 8;
    int d0 = idx & (DI - 1);
    int m = idx >> 11;
    int t = m & (LL - 1);
    const uint4* x8 = (const uint4*)xcraw;
    uint4 z4 = make_uint4(0u,0u,0u,0u);
    uint4 q0 = x8[i];
    uint4 q1 = (t >= 1) ? x8[i - DI/8]   : z4;
    uint4 q2 = (t >= 2) ? x8[i - 2*DI/8] : z4;
    uint4 q3 = (t >= 3) ? x8[i - 3*DI/8] : z4;
    const __half2* h0 = (const __half2*)&q0;
    const __half2* h1 = (const __half2*)&q1;
    const __half2* h2 = (const __half2*)&q2;
    const __half2* h3 = (const __half2*)&q3;
    uint4 outv;
    __half2* ov = (__half2*)&outv;
#pragma unroll
    for (int p = 0; p < 4; p++){
        int da = d0 + p*2, db = da + 1;
        float4 wA = ((const float4*)cw)[da];
        float4 wB = ((const float4*)cw)[db];
        float2 cb2 = ((const float2*)cb)[(d0 >> 1) + p];
        float xa0 = __low2float(h0[p]),  xb0 = __high2float(h0[p]);
        float xa1 = __low2float(h1[p]),  xb1 = __high2float(h1[p]);
        float xa2 = __low2float(h2[p]),  xb2 = __high2float(h2[p]);
        float xa3 = __low2float(h3[p]),  xb3 = __high2float(h3[p]);
        float sa = cb2.x + wA.w*xa0 + wA.z*xa1 + wA.y*xa2 + wA.x*xa3;
        float sbv = cb2.y + wB.w*xb0 + wB.z*xb1 + wB.y*xb2 + wB.x*xb3;
        ov[p] = __floats2half2_rn(squareplus_f(sa), squareplus_f(sbv));
    }
    ((uint4*)u)[i] = outv;
}

// ---------------- chunked scan (coalesced, 2 ch/thread) ----------------------
__global__ void k_scan(const __half* __restrict__ u,
                       const unsigned short* __restrict__ a16,
                       const __half* __restrict__ spz,
                       __half* __restrict__ y){
    const int tx = threadIdx.x;
    const int c0 = (blockIdx.x * 32 + tx) * 2;
    const int b = blockIdx.y;
    const int slice = threadIdx.y;
    const int CH = LL / 32;                        // 64
    size_t base = ((size_t)b * LL) * DI + c0;
    int t0 = slice * CH;

    float A0 = 1.0f, B0 = 0.0f, A1 = 1.0f, B1 = 0.0f;
    size_t idx = base + (size_t)t0 * DI;
    for (int t = 0; t < CH; t++, idx += DI){
        uint32_t aa = *(const uint32_t*)(a16 + idx);
        float at0 = (float)(aa & 0xFFFFu) * (1.0f/32768.0f);
        float at1 = (float)(aa >> 16)     * (1.0f/32768.0f);
        __half2 uh = *(const __half2*)(u + idx);
        float u0 = __low2float(uh), u1 = __high2float(uh);
        B0 = at0 * B0 + (1.0f - at0) * u0; A0 *= at0;
        B1 = at1 * B1 + (1.0f - at1) * u1; A1 *= at1;
    }
    __shared__ float2 sA[32][32], sB[32][32], sP[32][32];
    sA[slice][tx] = make_float2(A0, A1);
    sB[slice][tx] = make_float2(B0, B1);
    __syncthreads();
    if (slice == 0){
        float2 carry = make_float2(0.0f, 0.0f);
#pragma unroll
        for (int s2 = 0; s2 < 32; s2++){
            sP[s2][tx] = carry;
            float2 a = sA[s2][tx], bb = sB[s2][tx];
            carry.x = a.x * carry.x + bb.x;
            carry.y = a.y * carry.y + bb.y;
        }
    }
    __syncthreads();
    float2 h = sP[slice][tx];
    idx = base + (size_t)t0 * DI;
    for (int t = 0; t < CH; t++, idx += DI){
        uint32_t aa = *(const uint32_t*)(a16 + idx);
        float at0 = (float)(aa & 0xFFFFu) * (1.0f/32768.0f);
        float at1 = (float)(aa >> 16)     * (1.0f/32768.0f);
        __half2 uh = *(const __half2*)(u + idx);
        h.x = at0 * h.x + (1.0f - at0) * __low2float(uh);
        h.y = at1 * h.y + (1.0f - at1) * __high2float(uh);
        __half2 sz = *(const __half2*)(spz + idx);
        __half2 yy = __floats2half2_rn(h.x * __low2float(sz), h.y * __high2float(sz));
        *(__half2*)(y + idx) = yy;
    }
}

// ---------------- launch ------------------------------------------------------
extern "C" void kernel_launch(void* const* d_in, const int* in_sizes, int n_in,
                              void* d_out, int out_size){
    const float* x     = (const float*)d_in[0];
    const float* gamma = (const float*)d_in[1];
    const float* step  = (const float*)d_in[2];
    const float* W_in  = (const float*)d_in[3];
    const float* cw    = (const float*)d_in[4];
    const float* cb    = (const float*)d_in[5];
    const float* W_x   = (const float*)d_in[6];
    const float* W_dt  = (const float*)d_in[7];
    const float* b_dt  = (const float*)d_in[8];
    const float* W_out = (const float*)d_in[9];
    float* out = (float*)d_out;

    __half *p_xn, *p_xcraw, *p_spz, *p_u, *p_dbl, *p_y;
    __half *p_tin, *p_tx, *p_tdt, *p_tout;
    float *p_scale, *p_part;
    unsigned short* p_decay;
    cudaGetSymbolAddress((void**)&p_xn,    g_xn);
    cudaGetSymbolAddress((void**)&p_xcraw, g_xcraw);
    cudaGetSymbolAddress((void**)&p_spz,   g_spz);
    cudaGetSymbolAddress((void**)&p_u,     g_u);
    cudaGetSymbolAddress((void**)&p_dbl,   g_dbl);
    cudaGetSymbolAddress((void**)&p_decay, g_decay16);
    cudaGetSymbolAddress((void**)&p_y,     g_y);
    cudaGetSymbolAddress((void**)&p_tin,   g_t_in);
    cudaGetSymbolAddress((void**)&p_tx,    g_t_x);
    cudaGetSymbolAddress((void**)&p_tdt,   g_t_dt);
    cudaGetSymbolAddress((void**)&p_tout,  g_t_out);
    cudaGetSymbolAddress((void**)&p_scale, g_scale);
    cudaGetSymbolAddress((void**)&p_part,  g_part);

    const int SM128 = 4*(128*RSG + 128*RSG)*2;   // 81920
    const int SM64  = 4*( 64*RSG +  64*RSG)*2;   // 40960
    cudaFuncSetAttribute(k_gemm_h<128,128,4>, cudaFuncAttributeMaxDynamicSharedMemorySize, SM128);
    cudaFuncSetAttribute(k_gemm_h< 64, 64,3>, cudaFuncAttributeMaxDynamicSharedMemorySize, SM64);
    cudaFuncSetAttribute(k_gemm_h<128,128,1>, cudaFuncAttributeMaxDynamicSharedMemorySize, SM128);
    cudaFuncSetAttribute(k_gemm_h<128,128,2>, cudaFuncAttributeMaxDynamicSharedMemorySize, SM128);

    // per-half pointer offsets (half = 4096 rows = 2 full batches)
    const size_t OFF_DM = (size_t)MH * DM;   // fp32/fp16 x-rows
    const size_t OFF_DI = (size_t)MH * DI;
    const size_t OFF_DT = (size_t)MH * DTR;

    cudaStream_t s1, s2;
    cudaStreamCreateWithFlags(&s1, cudaStreamNonBlocking);
    cudaStreamCreateWithFlags(&s2, cudaStreamNonBlocking);
    cudaEvent_t e0, e_in, e_w, e_g0, e_c0;
    cudaEventCreateWithFlags(&e0,   cudaEventDisableTiming);
    cudaEventCreateWithFlags(&e_in, cudaEventDisableTiming);
    cudaEventCreateWithFlags(&e_w,  cudaEventDisableTiming);
    cudaEventCreateWithFlags(&e_g0, cudaEventDisableTiming);
    cudaEventCreateWithFlags(&e_c0, cudaEventDisableTiming);

    cudaEventRecord(e0, 0);
    cudaStreamWaitEvent(s1, e0, 0);

    // s1: scales + quantization
    k_abs4<<<dim3(256,4),256,0,s1>>>(W_in, W_x, W_dt, W_out,
                                     4096*1024/4, 96*2048/4, 2048*64/4, 1024*2048/4, p_part);
    k_absfin4<<<4,256,0,s1>>>(p_part, 1.0f/4194304.0f, 1.0f/196608.0f,
                              1.0f/131072.0f, 1.0f/2097152.0f, p_scale);
    k_quant<<<1024,256,0,s1>>>(W_in, p_tin, 4194304/4, p_scale + 0);
    cudaEventRecord(e_in, s1);
    k_quant<<<128,256,0,s1>>>(W_x,  p_tx,  131072/4,  p_scale + 1);
    k_quant<<<128,256,0,s1>>>(W_dt, p_tdt, 131072/4,  p_scale + 2);
    k_quant<<<512,256,0,s1>>>(W_out,p_tout,2097152/4, p_scale + 3);
    cudaEventRecord(e_w, s1);

    // s0: norm (all rows) overlaps quant chain
    k_norm<<<M_TOK/8,256>>>(x, gamma, step, p_xn);
    cudaStreamWaitEvent(0, e_in, 0);

    // s0: GEMM1 half 0 (rows 0..4095)
    k_gemm_h<128,128,4><<<dim3(32,32),256,SM128>>>(p_xn, p_tin, MH, 4096, 1024,
                                                   p_scale+0, nullptr, nullptr,
                                                   nullptr, p_xcraw, p_spz, nullptr);
    cudaEventRecord(e_g0, 0);

    // s0: GEMM1 half 1
    k_gemm_h<128,128,4><<<dim3(32,32),256,SM128>>>(p_xn + OFF_DM, p_tin, MH, 4096, 1024,
                                                   p_scale+0, nullptr, nullptr,
                                                   nullptr, p_xcraw + OFF_DI, p_spz + OFF_DI, nullptr);

    // s2: chain half 0 overlaps GEMM1 half 1
    cudaStreamWaitEvent(s2, e_g0, 0);
    cudaStreamWaitEvent(s2, e_w, 0);
    k_conv<<<MH*DI/8/256,256,0,s2>>>(p_xcraw, cw, cb, p_u);
    k_gemm_h<64,64,3><<<dim3(1,64),256,SM64,s2>>>(p_u, p_tx, MH, 64, 2048,
                                                  p_scale+1, nullptr, nullptr,
                                                  nullptr, p_dbl, nullptr, nullptr);
    k_gemm_h<128,128,1><<<dim3(16,32),256,SM128,s2>>>(p_dbl, p_tdt, MH, 2048, 64,
                                                      p_scale+2, b_dt, nullptr,
                                                      nullptr, nullptr, nullptr, p_decay);
    k_scan<<<dim3(DI/64, 2), dim3(32,32),0,s2>>>(p_u, p_decay, p_spz, p_y);
    k_gemm_h<128,128,2><<<dim3(8,32),256,SM128,s2>>>(p_y, p_tout, MH, 1024, 2048,
                                                     p_scale+3, nullptr, x,
                                                     out, nullptr, nullptr, nullptr);
    cudaEventRecord(e_c0, s2);

    // s0: chain half 1 (after GEMM1 half 1)
    cudaStreamWaitEvent(0, e_w, 0);
    k_conv<<<MH*DI/8/256,256>>>(p_xcraw + OFF_DI, cw, cb, p_u + OFF_DI);
    k_gemm_h<64,64,3><<<dim3(1,64),256,SM64>>>(p_u + OFF_DI, p_tx, MH, 64, 2048,
                                               p_scale+1, nullptr, nullptr,
                                               nullptr, p_dbl + OFF_DT, nullptr, nullptr);
    k_gemm_h<128,128,1><<<dim3(16,32),256,SM128>>>(p_dbl + OFF_DT, p_tdt, MH, 2048, 64,
                                                   p_scale+2, b_dt, nullptr,
                                                   nullptr, nullptr, nullptr, p_decay + OFF_DI);
    k_scan<<<dim3(DI/64, 2), dim3(32,32)>>>(p_u + OFF_DI, p_decay + OFF_DI,
                                            p_spz + OFF_DI, p_y + OFF_DI);
    k_gemm_h<128,128,2><<<dim3(8,32),256,SM128>>>(p_y + OFF_DI, p_tout, MH, 1024, 2048,
                                                  p_scale+3, nullptr, x + OFF_DM,
                                                  out + OFF_DM, nullptr, nullptr, nullptr);

    // join
    cudaStreamWaitEvent(0, e_c0, 0);

    cudaEventDestroy(e0);
    cudaEventDestroy(e_in);
    cudaEventDestroy(e_w);
    cudaEventDestroy(e_g0);
    cudaEventDestroy(e_c0);
    cudaStreamDestroy(s1);
    cudaStreamDestroy(s2);
}